// round 7
// baseline (speedup 1.0000x reference)
#include <cuda_runtime.h>

typedef unsigned long long ull;

#define TX      32
#define TY      64
#define HALO    5
#define KW      11
#define RX      42          // TX + 2*HALO
#define RY      74          // TY + 2*HALO
#define PPX     43          // sxy pitch in (u,v) pairs (ull)
#define HP      33          // h-buffer pitch in float4
#define IMH     2048
#define IMW     2048
#define NCH     3
#define NTHREADS 256
#define GX      64          // 2048 / TX
#define GY      32          // 2048 / TY
#define NBLK    (GX*GY)

#define C1 1.0e-4f
#define C2 9.0e-4f

// per-channel smem layout (floats)
#define OFS_SXY  0                              // RY*PPX ull = 6364 floats
#define OFS_H    (RY*PPX*2)                     // 6364
#define SMEM_FLOATS (OFS_H + RY*HP*4)           // +9768 = 16132 (64528 B)

#define WIDX(k) ((k) <= 5 ? (k) : (10 - (k)))   // symmetric Gaussian taps

__device__ float g_partial[NBLK];
__device__ unsigned int g_flag;   // zero-init; last block resets it

__device__ __forceinline__ ull pack2(float lo, float hi) {
    ull r; asm("mov.b64 %0,{%1,%2};" : "=l"(r) : "f"(lo), "f"(hi)); return r;
}
__device__ __forceinline__ float2 unpack2(ull v) {
    float2 r; asm("mov.b64 {%0,%1},%2;" : "=f"(r.x), "=f"(r.y) : "l"(v)); return r;
}
__device__ __forceinline__ ull fma2(ull a, ull b, ull c) {
    ull d; asm("fma.rn.f32x2 %0,%1,%2,%3;" : "=l"(d) : "l"(a), "l"(b), "l"(c)); return d;
}
__device__ __forceinline__ ull mul2(ull a, ull b) {
    ull d; asm("mul.rn.f32x2 %0,%1,%2;" : "=l"(d) : "l"(a), "l"(b)); return d;
}

__device__ __forceinline__ void load_channel(
    const float* __restrict__ img1, const float* __restrict__ img2,
    float* __restrict__ sxyF, int c, int row0, int col0, int tid)
{
    for (int idx = tid; idx < RY * RX; idx += NTHREADS) {
        int r = idx / RX;
        int p = idx - r * RX;
        int gr = row0 + r, gc = col0 + p;
        float v1 = 0.f, v2 = 0.f;
        if (gr >= 0 && gr < IMH && gc >= 0 && gc < IMW) {
            int off = (gr * IMW + gc) * NCH + c;
            v1 = img1[off];
            v2 = img2[off];
        }
        // zero padding commutes with (u,v) = (x+y, x-y)
        ((float2*)sxyF)[r * PPX + p] = make_float2(v1 + v2, v1 - v2);
    }
}

__global__ __launch_bounds__(NTHREADS, 3) void ssim_tile_kernel(
    const float* __restrict__ img1,
    const float* __restrict__ img2,
    const float* __restrict__ window,
    float* __restrict__ out)
{
    extern __shared__ float smem[];
    float* sxyF = smem + OFS_SXY;                // (u,v) pairs, one channel
    float* hF   = smem + OFS_H;                  // (U,V,Su,Sv) float4 per column

    const int tid  = threadIdx.x;
    const int wid  = tid >> 5;
    const int lane = tid & 31;

    // ---- separable taps (symmetric): g_k = w2d[5][k] / sqrt(w2d[5][5]), k<=5
    ull wwr[6];
    {
        float g5 = sqrtf(window[5 * KW + 5]);
        #pragma unroll
        for (int k = 0; k < 6; k++) {
            float w = window[5 * KW + k] / g5;
            wwr[k] = pack2(w, w);
        }
    }

    const int row0 = (int)blockIdx.y * TY - HALO;
    const int col0 = (int)blockIdx.x * TX - HALO;

    float lsum = 0.f;

    // prologue: channel 0
    load_channel(img1, img2, sxyF, 0, row0, col0, tid);
    __syncthreads();

    for (int c = 0; c < NCH; c++) {
        // ---------- horizontal pass: 8-wide register-blocked (296 items) ------
        for (int idx = tid; idx < RY * 4; idx += NTHREADS) {
            int r  = idx % RY;
            int j0 = (idx / RY) << 3;
            const ull* puv = (const ull*)sxyF + r * PPX + j0;

            ull auv[8], ass[8];
            #pragma unroll
            for (int o = 0; o < 8; o++) { auv[o] = 0; ass[o] = 0; }

            #pragma unroll
            for (int t = 0; t < 18; t++) {        // 8 + KW - 1
                ull vuv = puv[t];
                ull vss = mul2(vuv, vuv);
                #pragma unroll
                for (int o = 0; o < 8; o++) {
                    int k = t - o;
                    if (k >= 0 && k < KW) {       // compile-time resolved
                        auv[o] = fma2(wwr[WIDX(k)], vuv, auv[o]);
                        ass[o] = fma2(wwr[WIDX(k)], vss, ass[o]);
                    }
                }
            }
            float4* dst = (float4*)hF + r * HP + j0;
            #pragma unroll
            for (int o = 0; o < 8; o++) {
                float2 a = unpack2(auv[o]);
                float2 b = unpack2(ass[o]);
                dst[o] = make_float4(a.x, a.y, b.x, b.y);
            }
        }
        __syncthreads();   // sxy reads done; h writes visible

        // ---------- vertical pass: exact single wave (32 cols x 8 warps) ------
        {
            int tx  = lane;                       // column 0..31
            int ty0 = wid << 3;                   // stack base row 0..56
            ull aU[8], aS[8];
            #pragma unroll
            for (int o = 0; o < 8; o++) { aU[o] = 0; aS[o] = 0; }

            #pragma unroll
            for (int t = 0; t < 18; t++) {
                int r = ty0 + t;
                float4 h = ((const float4*)hF)[r * HP + tx];
                ull huv = pack2(h.x, h.y);
                ull hss = pack2(h.z, h.w);
                #pragma unroll
                for (int o = 0; o < 8; o++) {
                    int k = t - o;
                    if (k >= 0 && k < KW) {
                        aU[o] = fma2(wwr[WIDX(k)], huv, aU[o]);
                        aS[o] = fma2(wwr[WIDX(k)], hss, aS[o]);
                    }
                }
            }
            #pragma unroll
            for (int o = 0; o < 8; o++) {
                float2 uv = unpack2(aU[o]);      // U = mu1+mu2, V = mu1-mu2
                float2 ss = unpack2(aS[o]);      // Su = E[u^2], Sv = E[v^2]
                float U2 = uv.x * uv.x;
                float V2 = uv.y * uv.y;
                float A  = ss.x - U2;            // = s1+s2+2*s12 (x2 scale)
                float B  = ss.y - V2;            // = s1+s2-2*s12 (x2 scale)
                float num = fmaf(0.5f, U2 - V2, C1) * fmaf(0.5f, A - B, C2);
                float den = fmaf(0.5f, U2 + V2, C1) * fmaf(0.5f, A + B, C2);
                lsum += __fdividef(num, den);
            }
        }

        // ---------- overlap: next channel load (sxy) runs with vert tail ------
        if (c + 1 < NCH)
            load_channel(img1, img2, sxyF, c + 1, row0, col0, tid);

        __syncthreads();   // h reads done (next horiz rewrites h); sxy(c+1) visible
    }

    // ---------- block reduction ----------
    #pragma unroll
    for (int s = 16; s > 0; s >>= 1)
        lsum += __shfl_xor_sync(0xffffffffu, lsum, s);
    __shared__ float red[8];
    if (lane == 0) red[wid] = lsum;
    __syncthreads();
    if (tid == 0) {
        float bs = 0.f;
        #pragma unroll
        for (int i = 0; i < 8; i++) bs += red[i];
        g_partial[blockIdx.y * GX + blockIdx.x] = bs;
    }

    // ---------- last-block finalize (no second launch) ----------
    __shared__ bool amLast;
    __threadfence();
    if (tid == 0) {
        unsigned int n = atomicAdd(&g_flag, 1u);
        amLast = (n == (unsigned)(NBLK - 1));
    }
    __syncthreads();
    if (amLast) {
        double s = 0.0;
        for (int i = tid; i < NBLK; i += NTHREADS)
            s += (double)g_partial[i];
        #pragma unroll
        for (int sft = 16; sft > 0; sft >>= 1)
            s += __shfl_xor_sync(0xffffffffu, s, sft);
        __shared__ double rd[8];
        if (lane == 0) rd[wid] = s;
        __syncthreads();
        if (tid == 0) {
            double t = 0.0;
            #pragma unroll
            for (int i = 0; i < 8; i++) t += rd[i];
            out[0] = (float)(1.0 - t / ((double)IMH * IMW * NCH));
            g_flag = 0;                 // reset for next graph replay
        }
    }
}

extern "C" void kernel_launch(void* const* d_in, const int* in_sizes, int n_in,
                              void* d_out, int out_size)
{
    const float* img1 = (const float*)d_in[0];
    const float* img2 = (const float*)d_in[1];
    const float* win  = (const float*)d_in[2];
    float* out = (float*)d_out;
    (void)in_sizes; (void)n_in; (void)out_size;

    const size_t SMEM = (size_t)SMEM_FLOATS * sizeof(float);   // 64528 B
    cudaFuncSetAttribute(ssim_tile_kernel,
                         cudaFuncAttributeMaxDynamicSharedMemorySize, (int)SMEM);

    dim3 grid(GX, GY);
    ssim_tile_kernel<<<grid, NTHREADS, SMEM>>>(img1, img2, win, out);
}

// round 8
// speedup vs baseline: 1.0582x; 1.0582x over previous
#include <cuda_runtime.h>

typedef unsigned long long ull;

#define TS      32          // square tile
#define HALO    5
#define KW      11
#define RN      42          // TS + 2*HALO
#define PPX     43          // sxy pitch in (u,v) pairs (ull)
#define HP      33          // h-buffer pitch in float4
#define IMH     2048
#define IMW     2048
#define NCH     3
#define NTHREADS 128
#define GX      64
#define GY      64
#define NBLK    (GX*GY)

#define C1 1.0e-4f
#define C2 9.0e-4f

// per-channel smem layout (floats)
#define OFS_SXY  0                              // RN*PPX ull = 3612 floats
#define OFS_H    (RN*PPX*2)                     // 3612
#define SMEM_FLOATS (OFS_H + RN*HP*4)           // +5544 = 9156 (36624 B)

#define WIDX(k) ((k) <= 5 ? (k) : (10 - (k)))   // symmetric Gaussian taps

__device__ float g_partial[NBLK];
__device__ unsigned int g_flag;   // zero-init; last block resets it

__device__ __forceinline__ ull pack2(float lo, float hi) {
    ull r; asm("mov.b64 %0,{%1,%2};" : "=l"(r) : "f"(lo), "f"(hi)); return r;
}
__device__ __forceinline__ float2 unpack2(ull v) {
    float2 r; asm("mov.b64 {%0,%1},%2;" : "=f"(r.x), "=f"(r.y) : "l"(v)); return r;
}
__device__ __forceinline__ ull fma2(ull a, ull b, ull c) {
    ull d; asm("fma.rn.f32x2 %0,%1,%2,%3;" : "=l"(d) : "l"(a), "l"(b), "l"(c)); return d;
}
__device__ __forceinline__ ull mul2(ull a, ull b) {
    ull d; asm("mul.rn.f32x2 %0,%1,%2;" : "=l"(d) : "l"(a), "l"(b)); return d;
}

__global__ __launch_bounds__(NTHREADS, 6) void ssim_tile_kernel(
    const float* __restrict__ img1,
    const float* __restrict__ img2,
    const float* __restrict__ window,
    float* __restrict__ out)
{
    extern __shared__ float smem[];
    float* sxyF = smem + OFS_SXY;                // (u,v) pairs, one channel
    float* hF   = smem + OFS_H;                  // (U,V,Su,Sv) float4 per column

    const int tid  = threadIdx.x;
    const int wid  = tid >> 5;
    const int lane = tid & 31;

    // ---- separable taps (symmetric): g_k = w2d[5][k] / sqrt(w2d[5][5]), k<=5
    ull wwr[6];
    {
        float g5 = sqrtf(window[5 * KW + 5]);
        #pragma unroll
        for (int k = 0; k < 6; k++) {
            float w = window[5 * KW + k] / g5;
            wwr[k] = pack2(w, w);
        }
    }

    const int row0 = (int)blockIdx.y * TS - HALO;
    const int col0 = (int)blockIdx.x * TS - HALO;

    float lsum = 0.f;

    for (int c = 0; c < NCH; c++) {
        // ---------- per-channel load: HWC global -> (u,v) pairs in smem -------
        for (int idx = tid; idx < RN * RN; idx += NTHREADS) {
            int r = idx / RN;
            int p = idx - r * RN;
            int gr = row0 + r, gc = col0 + p;
            float v1 = 0.f, v2 = 0.f;
            if (gr >= 0 && gr < IMH && gc >= 0 && gc < IMW) {
                int off = (gr * IMW + gc) * NCH + c;
                v1 = img1[off];
                v2 = img2[off];
            }
            // zero padding commutes with (u,v) = (x+y, x-y)
            ((float2*)sxyF)[r * PPX + p] = make_float2(v1 + v2, v1 - v2);
        }
        __syncthreads();

        // ---------- horizontal pass: 8-wide register-blocked (168 items) ------
        for (int idx = tid; idx < RN * 4; idx += NTHREADS) {
            int r  = idx % RN;
            int j0 = (idx / RN) << 3;
            const ull* puv = (const ull*)sxyF + r * PPX + j0;

            ull auv[8], ass[8];
            #pragma unroll
            for (int o = 0; o < 8; o++) { auv[o] = 0; ass[o] = 0; }

            #pragma unroll
            for (int t = 0; t < 18; t++) {        // 8 + KW - 1
                ull vuv = puv[t];
                ull vss = mul2(vuv, vuv);
                #pragma unroll
                for (int o = 0; o < 8; o++) {
                    int k = t - o;
                    if (k >= 0 && k < KW) {       // compile-time resolved
                        auv[o] = fma2(wwr[WIDX(k)], vuv, auv[o]);
                        ass[o] = fma2(wwr[WIDX(k)], vss, ass[o]);
                    }
                }
            }
            float4* dst = (float4*)hF + r * HP + j0;
            #pragma unroll
            for (int o = 0; o < 8; o++) {
                float2 a = unpack2(auv[o]);
                float2 b = unpack2(ass[o]);
                dst[o] = make_float4(a.x, a.y, b.x, b.y);
            }
        }
        __syncthreads();   // sxy reads done; h writes visible

        // ---------- vertical pass: exact single wave (32 cols x 4 warps) ------
        {
            int tx  = lane;                       // column 0..31
            int ty0 = wid << 3;                   // stack base row 0/8/16/24
            ull aU[8], aS[8];
            #pragma unroll
            for (int o = 0; o < 8; o++) { aU[o] = 0; aS[o] = 0; }

            #pragma unroll
            for (int t = 0; t < 18; t++) {
                int r = ty0 + t;
                float4 h = ((const float4*)hF)[r * HP + tx];
                ull huv = pack2(h.x, h.y);
                ull hss = pack2(h.z, h.w);
                #pragma unroll
                for (int o = 0; o < 8; o++) {
                    int k = t - o;
                    if (k >= 0 && k < KW) {
                        aU[o] = fma2(wwr[WIDX(k)], huv, aU[o]);
                        aS[o] = fma2(wwr[WIDX(k)], hss, aS[o]);
                    }
                }
            }
            #pragma unroll
            for (int o = 0; o < 8; o++) {
                float2 uv = unpack2(aU[o]);      // U = mu1+mu2, V = mu1-mu2
                float2 ss = unpack2(aS[o]);      // Su = E[u^2], Sv = E[v^2]
                float U2 = uv.x * uv.x;
                float V2 = uv.y * uv.y;
                float A  = ss.x - U2;            // = s1+s2+2*s12 (x2 scale)
                float B  = ss.y - V2;            // = s1+s2-2*s12 (x2 scale)
                float num = fmaf(0.5f, U2 - V2, C1) * fmaf(0.5f, A - B, C2);
                float den = fmaf(0.5f, U2 + V2, C1) * fmaf(0.5f, A + B, C2);
                lsum += __fdividef(num, den);
            }
        }
        __syncthreads();   // h reads done before next channel overwrites sxy/h
    }

    // ---------- block reduction (4 warps) ----------
    #pragma unroll
    for (int s = 16; s > 0; s >>= 1)
        lsum += __shfl_xor_sync(0xffffffffu, lsum, s);
    __shared__ float red[4];
    if (lane == 0) red[wid] = lsum;
    __syncthreads();
    if (tid == 0) {
        float bs = red[0] + red[1] + red[2] + red[3];
        g_partial[blockIdx.y * GX + blockIdx.x] = bs;
    }

    // ---------- last-block finalize (no second launch) ----------
    __shared__ bool amLast;
    __threadfence();
    if (tid == 0) {
        unsigned int n = atomicAdd(&g_flag, 1u);
        amLast = (n == (unsigned)(NBLK - 1));
    }
    __syncthreads();
    if (amLast) {
        double s = 0.0;
        for (int i = tid; i < NBLK; i += NTHREADS)
            s += (double)g_partial[i];
        #pragma unroll
        for (int sft = 16; sft > 0; sft >>= 1)
            s += __shfl_xor_sync(0xffffffffu, s, sft);
        __shared__ double rd[4];
        if (lane == 0) rd[wid] = s;
        __syncthreads();
        if (tid == 0) {
            double t = rd[0] + rd[1] + rd[2] + rd[3];
            out[0] = (float)(1.0 - t / ((double)IMH * IMW * NCH));
            g_flag = 0;                 // reset for next graph replay
        }
    }
}

extern "C" void kernel_launch(void* const* d_in, const int* in_sizes, int n_in,
                              void* d_out, int out_size)
{
    const float* img1 = (const float*)d_in[0];
    const float* img2 = (const float*)d_in[1];
    const float* win  = (const float*)d_in[2];
    float* out = (float*)d_out;
    (void)in_sizes; (void)n_in; (void)out_size;

    const size_t SMEM = (size_t)SMEM_FLOATS * sizeof(float);   // 36624 B
    cudaFuncSetAttribute(ssim_tile_kernel,
                         cudaFuncAttributeMaxDynamicSharedMemorySize, (int)SMEM);

    dim3 grid(GX, GY);
    ssim_tile_kernel<<<grid, NTHREADS, SMEM>>>(img1, img2, win, out);
}